// round 17
// baseline (speedup 1.0000x reference)
#include <cuda_runtime.h>
#include <cuda_bf16.h>
#include <cuda_fp16.h>
#include <cstdint>

#define NN 50000
#define EE 600000
#define DD 128

#define SCAN_B 512
#define NSCAN ((NN + SCAN_B - 1) / SCAN_B)   // 98 blocks

// ---- scratch (device globals) ----
__device__ float g_dinv[NN];
__device__ int   g_cnt[NN];
__device__ int   g_off[NN];      // per-block exclusive scan (block offset added by consumers)
__device__ int   g_bsum[NSCAN];  // block totals, then exclusive scan of them
__device__ int   g_ticket;       // last-block detection for fused scan
__device__ int   g_esrc[EE];
__device__ float g_enorm[EE];
__device__ __half g_h[NN * DD];                   // layer-1 GEMM output (gather payload)
__device__ __half g_h2[NN * DD];                  // layer-2 GEMM output (gather payload)
__device__ __nv_bfloat16 g_wimg[2][2][DD * DD];   // [layer][hi/lo] W^T as [n][k]

// ========== fused init: zero cnt/dinv/ticket + W split-bf16 conversion ==========
__global__ void initconv_kernel(const float* __restrict__ W1, const float* __restrict__ W2) {
    int i = blockIdx.x * blockDim.x + threadIdx.x;
    if (i == 0) g_ticket = 0;
    if (i < NN) { g_cnt[i] = 0; g_dinv[i] = 0.0f; }
    if (i < 2 * DD * DD) {
        int layer = i >> 14;
        int kn = i & (DD * DD - 1);
        int k = kn >> 7, n = kn & 127;
        const float* W = layer ? W2 : W1;
        float v = W[k * DD + n];
        __nv_bfloat16 hi = __float2bfloat16(v);
        __nv_bfloat16 lo = __float2bfloat16(v - __bfloat162float(hi));
        g_wimg[layer][0][n * DD + k] = hi;
        g_wimg[layer][1][n * DD + k] = lo;
    }
}

__global__ void deg_hist_kernel(const int* __restrict__ ei, const float* __restrict__ ew) {
    int e = blockIdx.x * blockDim.x + threadIdx.x;
    if (e < EE) {
        int dst = ei[EE + e];
        atomicAdd(&g_dinv[dst], ew[e]);
        atomicAdd(&g_cnt[dst], 1);
    }
}

// shfl-based per-block exclusive scan of g_cnt -> g_off ; block totals -> g_bsum.
// fused: dinv finalize + cnt reset + (last block) exclusive scan of g_bsum.
__global__ void scan1_kernel() {
    __shared__ int wsum[16];
    __shared__ int s2[128];
    __shared__ int isLast;
    int tid = threadIdx.x;
    int lane = tid & 31;
    int wid = tid >> 5;
    int i = blockIdx.x * SCAN_B + tid;
    int v = (i < NN) ? g_cnt[i] : 0;

    // warp inclusive scan
    int xs = v;
#pragma unroll
    for (int d = 1; d < 32; d <<= 1) {
        int t = __shfl_up_sync(0xffffffffu, xs, d);
        if (lane >= d) xs += t;
    }
    if (lane == 31) wsum[wid] = xs;
    __syncthreads();
    if (wid == 0) {
        int ws = (lane < 16) ? wsum[lane] : 0;
#pragma unroll
        for (int d = 1; d < 16; d <<= 1) {
            int t = __shfl_up_sync(0xffffffffu, ws, d);
            if (lane >= d) ws += t;
        }
        if (lane < 16) wsum[lane] = ws;
    }
    __syncthreads();
    int incl = xs + (wid ? wsum[wid - 1] : 0);

    if (i < NN) {
        g_off[i] = incl - v;
        g_cnt[i] = 0;
        g_dinv[i] = rsqrtf(g_dinv[i] + 1.0f);
    }
    if (tid == SCAN_B - 1) g_bsum[blockIdx.x] = incl;

    // last-block: exclusive scan of the NSCAN block sums
    __threadfence();
    if (tid == 0) isLast = (atomicAdd(&g_ticket, 1) == gridDim.x - 1);
    __syncthreads();
    if (isLast) {
        int bv = (tid < NSCAN) ? g_bsum[tid] : 0;
        if (tid < 128) s2[tid] = bv;
        __syncthreads();
#pragma unroll
        for (int d = 1; d < 128; d <<= 1) {
            int t = (tid >= d && tid < 128) ? s2[tid - d] : 0;
            __syncthreads();
            if (tid < 128) s2[tid] += t;
            __syncthreads();
        }
        if (tid < NSCAN) g_bsum[tid] = s2[tid] - bv;
        if (tid == 0) g_ticket = 0;
    }
}

// bucket edges by dst (block offset resolved inline); fuse norm computation
__global__ void fill_kernel(const int* __restrict__ ei, const float* __restrict__ ew) {
    int e = blockIdx.x * blockDim.x + threadIdx.x;
    if (e >= EE) return;
    int src = ei[e];
    int dst = ei[EE + e];
    float nrm = g_dinv[src] * ew[e] * g_dinv[dst];
    int slot = g_off[dst] + g_bsum[dst >> 9] + atomicAdd(&g_cnt[dst], 1);
    g_esrc[slot] = src;
    g_enorm[slot] = nrm;
}

// ============ shared GEMM machinery ============
#define PADW 68
#define IMG_W (128 * PADW)
#define GEMM_SMEM (4 * IMG_W * 4)          // 139264 bytes

__device__ __forceinline__ void mma_bf16(float* c, uint32_t a0, uint32_t a1,
                                         uint32_t a2, uint32_t a3,
                                         uint32_t b0, uint32_t b1) {
    asm volatile(
        "mma.sync.aligned.m16n8k16.row.col.f32.bf16.bf16.f32 "
        "{%0,%1,%2,%3}, {%4,%5,%6,%7}, {%8,%9}, {%0,%1,%2,%3};"
        : "+f"(c[0]), "+f"(c[1]), "+f"(c[2]), "+f"(c[3])
        : "r"(a0), "r"(a1), "r"(a2), "r"(a3), "r"(b0), "r"(b1));
}

// load W images for `layer` into Bhi/Blo (all 256 threads)
__device__ __forceinline__ void load_w_images(uint32_t* Bhi, uint32_t* Blo,
                                              int layer, int tid) {
    const uint32_t* wh = reinterpret_cast<const uint32_t*>(g_wimg[layer][0]);
    const uint32_t* wl = reinterpret_cast<const uint32_t*>(g_wimg[layer][1]);
#pragma unroll
    for (int t = 0; t < 32; t++) {
        int idx = tid + t * 256;
        int n = idx >> 6, k2 = idx & 63;
        Bhi[n * PADW + k2] = wh[idx];
        Blo[n * PADW + k2] = wl[idx];
    }
}

// MMA mainloop + fp16 epilogue into dst
__device__ __forceinline__ void mma_and_store(const uint32_t* Ahi, const uint32_t* Alo,
                                              const uint32_t* Bhi, const uint32_t* Blo,
                                              __half* __restrict__ dst, int row0, int tid) {
    int w = tid >> 5, l = tid & 31;
    int g = l >> 2, q = l & 3;

    float acc[16][4];
#pragma unroll
    for (int nt = 0; nt < 16; nt++)
#pragma unroll
        for (int i = 0; i < 4; i++) acc[nt][i] = 0.0f;

    int arow = w * 16 + g;

    for (int kt = 0; kt < 8; kt++) {
        int kw = kt * 8 + q;
        uint32_t a0h = Ahi[arow * PADW + kw];
        uint32_t a1h = Ahi[(arow + 8) * PADW + kw];
        uint32_t a2h = Ahi[arow * PADW + kw + 4];
        uint32_t a3h = Ahi[(arow + 8) * PADW + kw + 4];
        uint32_t a0l = Alo[arow * PADW + kw];
        uint32_t a1l = Alo[(arow + 8) * PADW + kw];
        uint32_t a2l = Alo[arow * PADW + kw + 4];
        uint32_t a3l = Alo[(arow + 8) * PADW + kw + 4];

        uint32_t bh[16][2];
#pragma unroll
        for (int nt = 0; nt < 16; nt++) {
            int n = nt * 8 + g;
            bh[nt][0] = Bhi[n * PADW + kw];
            bh[nt][1] = Bhi[n * PADW + kw + 4];
            mma_bf16(acc[nt], a0h, a1h, a2h, a3h, bh[nt][0], bh[nt][1]);
        }
#pragma unroll
        for (int nt = 0; nt < 16; nt++)
            mma_bf16(acc[nt], a0l, a1l, a2l, a3l, bh[nt][0], bh[nt][1]);
#pragma unroll
        for (int nt = 0; nt < 16; nt++) {
            int n = nt * 8 + g;
            uint32_t b0 = Blo[n * PADW + kw];
            uint32_t b1 = Blo[n * PADW + kw + 4];
            mma_bf16(acc[nt], a0h, a1h, a2h, a3h, b0, b1);
        }
    }

    int r0 = row0 + w * 16 + g;
#pragma unroll
    for (int nt = 0; nt < 16; nt++) {
        int c = nt * 8 + q * 2;
        if (r0 < NN)
            *reinterpret_cast<__half2*>(&dst[(size_t)r0 * DD + c]) =
                __floats2half2_rn(acc[nt][0], acc[nt][1]);
        if (r0 + 8 < NN)
            *reinterpret_cast<__half2*>(&dst[(size_t)(r0 + 8) * DD + c]) =
                __floats2half2_rn(acc[nt][2], acc[nt][3]);
    }
}

// ============ layer-1 GEMM: g_h = x @ W1 ============
__global__ void __launch_bounds__(256, 1)
gemm1_kernel(const float* __restrict__ x) {
    extern __shared__ uint32_t sm[];
    uint32_t* Ahi = sm;
    uint32_t* Alo = Ahi + IMG_W;
    uint32_t* Bhi = Alo + IMG_W;
    uint32_t* Blo = Bhi + IMG_W;
    int tid = threadIdx.x;

    load_w_images(Bhi, Blo, 0, tid);
    {
        int row = tid >> 1, hf = tid & 1;
        int grow = blockIdx.x * 128 + row;
        bool ok = grow < NN;
        const float4* ar = reinterpret_cast<const float4*>(x + (size_t)(ok ? grow : 0) * DD) + hf * 16;
        uint32_t* dh = Ahi + row * PADW + hf * 32;
        uint32_t* dl = Alo + row * PADW + hf * 32;
#pragma unroll
        for (int j = 0; j < 16; j++) {
            float4 v = ok ? ar[j] : make_float4(0.f, 0.f, 0.f, 0.f);
            __nv_bfloat162 h01 = __floats2bfloat162_rn(v.x, v.y);
            __nv_bfloat162 h23 = __floats2bfloat162_rn(v.z, v.w);
            __nv_bfloat162 l01 = __floats2bfloat162_rn(v.x - __low2float(h01), v.y - __high2float(h01));
            __nv_bfloat162 l23 = __floats2bfloat162_rn(v.z - __low2float(h23), v.w - __high2float(h23));
            dh[2 * j]     = *reinterpret_cast<uint32_t*>(&h01);
            dh[2 * j + 1] = *reinterpret_cast<uint32_t*>(&h23);
            dl[2 * j]     = *reinterpret_cast<uint32_t*>(&l01);
            dl[2 * j + 1] = *reinterpret_cast<uint32_t*>(&l23);
        }
    }
    __syncthreads();
    mma_and_store(Ahi, Alo, Bhi, Blo, g_h, blockIdx.x * 128, tid);
}

// ============ fused: agg1(relu(A(g_h)+self+b1)) -> smem -> GEMM(W2) -> g_h2 ============
__global__ void __launch_bounds__(256, 1)
fused_agg_gemm2_kernel(const float* __restrict__ b1) {
    extern __shared__ uint32_t sm[];
    uint32_t* Ahi = sm;
    uint32_t* Alo = Ahi + IMG_W;
    uint32_t* Bhi = Alo + IMG_W;
    uint32_t* Blo = Bhi + IMG_W;
    int tid = threadIdx.x;
    int w = tid >> 5, lane = tid & 31;

    load_w_images(Bhi, Blo, 1, tid);

    // aggregation phase: warp per node, 16 nodes per warp
    const uint2* __restrict__ h2 = reinterpret_cast<const uint2*>(g_h);
    float4 bb = *reinterpret_cast<const float4*>(&b1[lane * 4]);
#pragma unroll 1
    for (int j = 0; j < 16; j++) {
        int lrow = w * 16 + j;
        int gw = blockIdx.x * 128 + lrow;
        float4 acc = make_float4(0.f, 0.f, 0.f, 0.f);
        if (gw < NN) {
            int beg = g_off[gw] + g_bsum[gw >> 9];
            int end = (gw + 1 < NN) ? (g_off[gw + 1] + g_bsum[(gw + 1) >> 9]) : EE;
            float di = g_dinv[gw];
            float d2 = di * di;
            uint2 su = h2[gw * 32 + lane];
            float2 s01 = __half22float2(*reinterpret_cast<__half2*>(&su.x));
            float2 s23 = __half22float2(*reinterpret_cast<__half2*>(&su.y));
            acc.x = d2 * s01.x + bb.x;
            acc.y = d2 * s01.y + bb.y;
            acc.z = d2 * s23.x + bb.z;
            acc.w = d2 * s23.y + bb.w;
            for (int e = beg; e < end; e++) {
                int src = g_esrc[e];
                float nrm = g_enorm[e];
                uint2 u = h2[src * 32 + lane];
                float2 f01 = __half22float2(*reinterpret_cast<__half2*>(&u.x));
                float2 f23 = __half22float2(*reinterpret_cast<__half2*>(&u.y));
                acc.x += nrm * f01.x;
                acc.y += nrm * f01.y;
                acc.z += nrm * f23.x;
                acc.w += nrm * f23.y;
            }
            acc.x = fmaxf(acc.x, 0.f);
            acc.y = fmaxf(acc.y, 0.f);
            acc.z = fmaxf(acc.z, 0.f);
            acc.w = fmaxf(acc.w, 0.f);
        }
        // split to bf16 hi/lo directly into A images (cols lane*4 .. lane*4+3)
        __nv_bfloat162 h01 = __floats2bfloat162_rn(acc.x, acc.y);
        __nv_bfloat162 h23 = __floats2bfloat162_rn(acc.z, acc.w);
        __nv_bfloat162 l01 = __floats2bfloat162_rn(acc.x - __low2float(h01), acc.y - __high2float(h01));
        __nv_bfloat162 l23 = __floats2bfloat162_rn(acc.z - __low2float(h23), acc.w - __high2float(h23));
        Ahi[lrow * PADW + lane * 2]     = *reinterpret_cast<uint32_t*>(&h01);
        Ahi[lrow * PADW + lane * 2 + 1] = *reinterpret_cast<uint32_t*>(&h23);
        Alo[lrow * PADW + lane * 2]     = *reinterpret_cast<uint32_t*>(&l01);
        Alo[lrow * PADW + lane * 2 + 1] = *reinterpret_cast<uint32_t*>(&l23);
    }
    __syncthreads();
    mma_and_store(Ahi, Alo, Bhi, Blo, g_h2, blockIdx.x * 128, tid);
}

// ================= layer-2 aggregate: g_h2 -> out (no relu) =================
__global__ __launch_bounds__(256)
void agg2_kernel(const float* __restrict__ b, float* __restrict__ outbuf) {
    int gw = (blockIdx.x * blockDim.x + threadIdx.x) >> 5;
    int lane = threadIdx.x & 31;
    if (gw >= NN) return;

    const uint2* __restrict__ h2 = reinterpret_cast<const uint2*>(g_h2);

    int beg = g_off[gw] + g_bsum[gw >> 9];
    int end = (gw + 1 < NN) ? (g_off[gw + 1] + g_bsum[(gw + 1) >> 9]) : EE;

    float di = g_dinv[gw];
    float d2 = di * di;
    float4 bb = *reinterpret_cast<const float4*>(&b[lane * 4]);

    uint2 su = h2[gw * 32 + lane];
    float2 s01 = __half22float2(*reinterpret_cast<__half2*>(&su.x));
    float2 s23 = __half22float2(*reinterpret_cast<__half2*>(&su.y));
    float4 acc;
    acc.x = d2 * s01.x + bb.x;
    acc.y = d2 * s01.y + bb.y;
    acc.z = d2 * s23.x + bb.z;
    acc.w = d2 * s23.y + bb.w;

    for (int e = beg; e < end; e++) {
        int src = g_esrc[e];
        float nrm = g_enorm[e];
        uint2 u = h2[src * 32 + lane];
        float2 f01 = __half22float2(*reinterpret_cast<__half2*>(&u.x));
        float2 f23 = __half22float2(*reinterpret_cast<__half2*>(&u.y));
        acc.x += nrm * f01.x;
        acc.y += nrm * f01.y;
        acc.z += nrm * f23.x;
        acc.w += nrm * f23.y;
    }

    *reinterpret_cast<float4*>(&outbuf[gw * DD + lane * 4]) = acc;
}

// ================= launch =================
extern "C" void kernel_launch(void* const* d_in, const int* in_sizes, int n_in,
                              void* d_out, int out_size) {
    const float* x  = (const float*)d_in[0];
    const int*   ei = (const int*)d_in[1];     // int32 (jax x64 disabled)
    const float* ew = (const float*)d_in[2];
    const float* W1 = (const float*)d_in[3];
    const float* b1 = (const float*)d_in[4];
    const float* W2 = (const float*)d_in[5];
    const float* b2 = (const float*)d_in[6];
    float* out = (float*)d_out;

    // one-time setup (no device memory allocated; launched work identical every call)
    static cudaStream_t s2;
    static cudaEvent_t ev_fork, ev_join;
    static bool once = false;
    if (!once) {
        cudaFuncSetAttribute(gemm1_kernel,
                             cudaFuncAttributeMaxDynamicSharedMemorySize, GEMM_SMEM);
        cudaFuncSetAttribute(fused_agg_gemm2_kernel,
                             cudaFuncAttributeMaxDynamicSharedMemorySize, GEMM_SMEM);
        cudaStreamCreateWithFlags(&s2, cudaStreamNonBlocking);
        cudaEventCreateWithFlags(&ev_fork, cudaEventDisableTiming);
        cudaEventCreateWithFlags(&ev_join, cudaEventDisableTiming);
        once = true;
    }

    const int NB_N  = (NN + 255) / 256;        // covers 2*DD*DD = 32768 too
    const int NB_E  = (EE + 255) / 256;
    const int NB_AG = (NN * 32 + 255) / 256;
    const int NB_GM = (NN + 127) / 128;        // 391 tiles

    // ---- prologue ----
    initconv_kernel<<<NB_N, 256>>>(W1, W2);

    // fork: gemm1 (depends only on initconv + x) concurrent with CSR build
    cudaEventRecord(ev_fork, 0);
    cudaStreamWaitEvent(s2, ev_fork, 0);
    gemm1_kernel<<<NB_GM, 256, GEMM_SMEM, s2>>>(x);
    cudaEventRecord(ev_join, s2);

    // main stream: CSR build
    deg_hist_kernel<<<NB_E, 256>>>(ei, ew);
    scan1_kernel<<<NSCAN, SCAN_B>>>();
    fill_kernel<<<NB_E, 256>>>(ei, ew);

    // join: fused kernel needs fill (stream order) and gemm1 (event)
    cudaStreamWaitEvent(0, ev_join, 0);

    // ---- layer 1 aggregate + layer 2 GEMM (fused) ----
    fused_agg_gemm2_kernel<<<NB_GM, 256, GEMM_SMEM>>>(b1);

    // ---- layer 2 aggregate ----
    agg2_kernel<<<NB_AG, 256>>>(b2, out);
}